// round 12
// baseline (speedup 1.0000x reference)
#include <cuda_runtime.h>
#include <cuda_bf16.h>
#include <math_constants.h>

#define E  512
#define L  1024
#define B2 512
#define CHUNK 128
#define NPART 32     // row-group partial count; scores folds these

__device__ float g_c;
__device__ float g_scores[B2 * L];       // raw attention energies
__device__ float g_partial[NPART * E];   // prep partials (folded by scores)

// ---------------------------------------------------------------------------
// Prep: grid (4 col-groups, 32 row-groups) x 128 threads.
// Block (cg, j) reduces W rows [16j, 16j+16) over columns [128cg, 128cg+128)
// into g_partial[j][e]. Block (0,0) also computes c = bias . wv.
// ---------------------------------------------------------------------------
__global__ __launch_bounds__(128)
void prep_kernel(const float* __restrict__ W,
                 const float* __restrict__ bias,
                 const float* __restrict__ wv) {
    __shared__ float s_wv[16];
    __shared__ float s_red[4];
    const int cg = blockIdx.x;          // 0..3
    const int j  = blockIdx.y;          // 0..NPART-1
    const int t  = threadIdx.x;         // 0..127
    const int e  = cg * 128 + t;
    const int f0 = j * 16;

    if (t < 16) s_wv[t] = __ldg(wv + f0 + t);
    __syncthreads();

    float acc = 0.f;
    #pragma unroll
    for (int r = 0; r < 16; ++r)
        acc = fmaf(__ldg(W + (size_t)(f0 + r) * E + e), s_wv[r], acc);
    g_partial[(size_t)j * E + e] = acc;

    if (cg == 0 && j == 0) {
        const int warp = t >> 5, lane = t & 31;
        float part = 0.f;
        #pragma unroll
        for (int f = t; f < E; f += 128)
            part = fmaf(__ldg(bias + f), __ldg(wv + f), part);
        #pragma unroll
        for (int o = 16; o; o >>= 1)
            part += __shfl_down_sync(0xffffffffu, part, o);
        if (lane == 0) s_red[warp] = part;
        __syncthreads();
        if (t == 0)
            g_c = s_red[0] + s_red[1] + s_red[2] + s_red[3];
    }
}

// ---------------------------------------------------------------------------
// Scores: grid (L/CHUNK, B2), 256 threads = 8 warps, 16 tokens per warp.
// PDL prelude: L2-prefetch this CTA's q chunk (input data, independent of
// prep) so DRAM streams during prep's window; then gridsync, fold partials,
// run the R2-proven hot loop (DO NOT modify).
// ---------------------------------------------------------------------------
__global__ __launch_bounds__(256)
void scores_kernel(const float* __restrict__ q,
                   const int* __restrict__ lens) {
    __shared__ float s_v[E];

    const int tid  = threadIdx.x;
    const int warp = tid >> 5;
    const int lane = tid & 31;
    const int b    = blockIdx.y;
    const int base = blockIdx.x * CHUNK;
    const int len  = lens[b];            // input, independent of prep

    const float* __restrict__ qrow = q + (size_t)b * L * E;
    const int tok_end = min(base + CHUNK, len);

    // ---- prelude: prefetch valid q chunk into L2 (128B lines) ----
    if (base < len) {
        const char* p = reinterpret_cast<const char*>(qrow + (size_t)base * E);
        const int nlines = (tok_end - base) * (E * 4 / 128);   // 16 lines/token
        for (int i = tid; i < nlines; i += 256)
            asm volatile("prefetch.global.L2 [%0];" :: "l"(p + (size_t)i * 128));
    }

    cudaGridDependencySynchronize();     // wait for g_partial / g_c

    if (base >= len) return;             // whole chunk masked out

    #pragma unroll
    for (int i = tid; i < E; i += 256) {
        float s = 0.f;
        #pragma unroll
        for (int jj = 0; jj < NPART; ++jj)
            s += g_partial[jj * E + i];
        s_v[i] = s;
    }
    __syncthreads();

    const float c = g_c;
    const float4* __restrict__ vv = reinterpret_cast<const float4*>(s_v);

    for (int l = base + warp * 16; l < min(base + warp * 16 + 16, tok_end); ++l) {
        const float4* __restrict__ qp =
            reinterpret_cast<const float4*>(qrow + (size_t)l * E);
        float acc = 0.f;
        #pragma unroll
        for (int k = 0; k < 4; ++k) {
            float4 a = __ldg(qp + k * 32 + lane);
            float4 w = vv[k * 32 + lane];
            acc = fmaf(a.x, w.x, acc);
            acc = fmaf(a.y, w.y, acc);
            acc = fmaf(a.z, w.z, acc);
            acc = fmaf(a.w, w.w, acc);
        }
        #pragma unroll
        for (int o = 16; o; o >>= 1)
            acc += __shfl_down_sync(0xffffffffu, acc, o);
        if (lane == 0) g_scores[b * L + l] = acc + c;
    }
}

// ---------------------------------------------------------------------------
// Softmax over valid prefix. One 256-thread block per row, float4 I/O.
// PDL: lens prelude before gridsync.
// ---------------------------------------------------------------------------
__global__ __launch_bounds__(256)
void softmax_kernel(const int* __restrict__ lens,
                    float* __restrict__ out) {
    __shared__ float s_red[8];
    __shared__ float s_bcast;

    const int tid  = threadIdx.x;
    const int warp = tid >> 5;
    const int lane = tid & 31;
    const int b    = blockIdx.x;
    const int len  = lens[b];            // input, independent of scores
    const int i0   = tid * 4;

    cudaGridDependencySynchronize();     // wait for g_scores

    float4 sc = *reinterpret_cast<const float4*>(g_scores + b * L + i0);
    float x0 = (i0 + 0 < len) ? sc.x : -CUDART_INF_F;
    float x1 = (i0 + 1 < len) ? sc.y : -CUDART_INF_F;
    float x2 = (i0 + 2 < len) ? sc.z : -CUDART_INF_F;
    float x3 = (i0 + 3 < len) ? sc.w : -CUDART_INF_F;

    float m = fmaxf(fmaxf(x0, x1), fmaxf(x2, x3));
    #pragma unroll
    for (int o = 16; o; o >>= 1)
        m = fmaxf(m, __shfl_down_sync(0xffffffffu, m, o));
    if (lane == 0) s_red[warp] = m;
    __syncthreads();
    if (warp == 0) {
        float t = (lane < 8) ? s_red[lane] : -CUDART_INF_F;
        #pragma unroll
        for (int o = 4; o; o >>= 1)
            t = fmaxf(t, __shfl_down_sync(0xffffffffu, t, o));
        if (lane == 0) s_bcast = t;
    }
    __syncthreads();
    const float rowmax = s_bcast;

    float e0 = (i0 + 0 < len) ? __expf(x0 - rowmax) : 0.f;
    float e1 = (i0 + 1 < len) ? __expf(x1 - rowmax) : 0.f;
    float e2 = (i0 + 2 < len) ? __expf(x2 - rowmax) : 0.f;
    float e3 = (i0 + 3 < len) ? __expf(x3 - rowmax) : 0.f;

    float s = e0 + e1 + e2 + e3;
    #pragma unroll
    for (int o = 16; o; o >>= 1)
        s += __shfl_down_sync(0xffffffffu, s, o);
    __syncthreads();
    if (lane == 0) s_red[warp] = s;
    __syncthreads();
    if (warp == 0) {
        float t = (lane < 8) ? s_red[lane] : 0.f;
        #pragma unroll
        for (int o = 4; o; o >>= 1)
            t += __shfl_down_sync(0xffffffffu, t, o);
        if (lane == 0) s_bcast = t;
    }
    __syncthreads();
    const float inv = 1.f / s_bcast;

    float4 r = make_float4(e0 * inv, e1 * inv, e2 * inv, e3 * inv);
    *reinterpret_cast<float4*>(out + (size_t)b * L + i0) = r;
}

extern "C" void kernel_launch(void* const* d_in, const int* in_sizes, int n_in,
                              void* d_out, int out_size) {
    const float* questions = (const float*)d_in[0];   // [B2, L, E]
    const int*   lens      = (const int*)d_in[1];     // [B2]
    const float* W         = (const float*)d_in[2];   // [E, E]
    const float* bias      = (const float*)d_in[3];   // [E]
    const float* wv        = (const float*)d_in[4];   // [E, 1]
    float* out             = (float*)d_out;           // [B2, L]

    prep_kernel<<<dim3(4, NPART), 128>>>(W, bias, wv);

    cudaLaunchAttribute attr[1];
    attr[0].id = cudaLaunchAttributeProgrammaticStreamSerialization;
    attr[0].val.programmaticStreamSerializationAllowed = 1;

    {   // scores with PDL
        cudaLaunchConfig_t cfg = {};
        cfg.gridDim  = dim3(L / CHUNK, B2);
        cfg.blockDim = dim3(256);
        cfg.stream   = 0;
        cfg.attrs    = attr;
        cfg.numAttrs = 1;
        cudaLaunchKernelEx(&cfg, scores_kernel, questions, lens);
    }
    {   // softmax with PDL
        cudaLaunchConfig_t cfg = {};
        cfg.gridDim  = dim3(B2);
        cfg.blockDim = dim3(256);
        cfg.stream   = 0;
        cfg.attrs    = attr;
        cfg.numAttrs = 1;
        cudaLaunchKernelEx(&cfg, softmax_kernel, lens, out);
    }
}

// round 13
// speedup vs baseline: 1.2989x; 1.2989x over previous
#include <cuda_runtime.h>
#include <cuda_bf16.h>
#include <math_constants.h>

#define E  512
#define L  1024
#define B2 512
#define CHUNK 128
#define NPART 16     // row-group partial count; scores folds these
#define PREFETCH_CTAS 128   // L2 budget: 128 CTAs x 256KB = 32MB << 126MB L2

__device__ float g_c;
__device__ float g_scores[B2 * L];       // raw attention energies
__device__ float g_partial[NPART * E];   // prep partials (folded by scores)

// ---------------------------------------------------------------------------
// Prep: grid (4 col-groups, 16 row-groups) x 128 threads.
// Block (cg, j) reduces W rows [32j, 32j+32) over columns [128cg, 128cg+128)
// into g_partial[j][e]. Block (0,0) also computes c = bias . wv.
// ---------------------------------------------------------------------------
__global__ __launch_bounds__(128)
void prep_kernel(const float* __restrict__ W,
                 const float* __restrict__ bias,
                 const float* __restrict__ wv) {
    __shared__ float s_wv[32];
    __shared__ float s_red[4];
    const int cg = blockIdx.x;          // 0..3
    const int j  = blockIdx.y;          // 0..NPART-1
    const int t  = threadIdx.x;         // 0..127
    const int e  = cg * 128 + t;
    const int f0 = j * 32;

    if (t < 32) s_wv[t] = __ldg(wv + f0 + t);
    __syncthreads();

    float acc = 0.f;
    #pragma unroll
    for (int r = 0; r < 32; ++r)
        acc = fmaf(__ldg(W + (size_t)(f0 + r) * E + e), s_wv[r], acc);
    g_partial[(size_t)j * E + e] = acc;

    if (cg == 0 && j == 0) {
        const int warp = t >> 5, lane = t & 31;
        float part = 0.f;
        #pragma unroll
        for (int f = t; f < E; f += 128)
            part = fmaf(__ldg(bias + f), __ldg(wv + f), part);
        #pragma unroll
        for (int o = 16; o; o >>= 1)
            part += __shfl_down_sync(0xffffffffu, part, o);
        if (lane == 0) s_red[warp] = part;
        __syncthreads();
        if (t == 0)
            g_c = s_red[0] + s_red[1] + s_red[2] + s_red[3];
    }
}

// ---------------------------------------------------------------------------
// Scores: grid (L/CHUNK, B2), 256 threads = 8 warps, 16 tokens per warp.
// PDL prelude: ONLY the first PREFETCH_CTAS linear CTAs (first wave, fits L2)
// prefetch their q chunk so DRAM streams during prep's window. Then gridsync,
// fold partials, run the R2-proven hot loop (DO NOT modify).
// ---------------------------------------------------------------------------
__global__ __launch_bounds__(256)
void scores_kernel(const float* __restrict__ q,
                   const int* __restrict__ lens) {
    __shared__ float s_v[E];

    const int tid  = threadIdx.x;
    const int warp = tid >> 5;
    const int lane = tid & 31;
    const int b    = blockIdx.y;
    const int base = blockIdx.x * CHUNK;
    const int len  = lens[b];            // input, independent of prep

    const float* __restrict__ qrow = q + (size_t)b * L * E;
    const int tok_end = min(base + CHUNK, len);
    const int linid = blockIdx.y * gridDim.x + blockIdx.x;

    // ---- prelude: budgeted L2 prefetch (first wave only) ----
    if (linid < PREFETCH_CTAS && base < len) {
        const char* p = reinterpret_cast<const char*>(qrow + (size_t)base * E);
        const int nlines = (tok_end - base) * (E * 4 / 128);   // 16 lines/token
        for (int i = tid; i < nlines; i += 256)
            asm volatile("prefetch.global.L2 [%0];" :: "l"(p + (size_t)i * 128));
    }

    cudaGridDependencySynchronize();     // wait for g_partial / g_c

    if (base >= len) return;             // whole chunk masked out

    #pragma unroll
    for (int i = tid; i < E; i += 256) {
        float s = 0.f;
        #pragma unroll
        for (int jj = 0; jj < NPART; ++jj)
            s += g_partial[jj * E + i];
        s_v[i] = s;
    }
    __syncthreads();

    const float c = g_c;
    const float4* __restrict__ vv = reinterpret_cast<const float4*>(s_v);

    for (int l = base + warp * 16; l < min(base + warp * 16 + 16, tok_end); ++l) {
        const float4* __restrict__ qp =
            reinterpret_cast<const float4*>(qrow + (size_t)l * E);
        float acc = 0.f;
        #pragma unroll
        for (int k = 0; k < 4; ++k) {
            float4 a = __ldg(qp + k * 32 + lane);
            float4 w = vv[k * 32 + lane];
            acc = fmaf(a.x, w.x, acc);
            acc = fmaf(a.y, w.y, acc);
            acc = fmaf(a.z, w.z, acc);
            acc = fmaf(a.w, w.w, acc);
        }
        #pragma unroll
        for (int o = 16; o; o >>= 1)
            acc += __shfl_down_sync(0xffffffffu, acc, o);
        if (lane == 0) g_scores[b * L + l] = acc + c;
    }
}

// ---------------------------------------------------------------------------
// Softmax over valid prefix. One 256-thread block per row, float4 I/O.
// PDL: lens prelude before gridsync.
// ---------------------------------------------------------------------------
__global__ __launch_bounds__(256)
void softmax_kernel(const int* __restrict__ lens,
                    float* __restrict__ out) {
    __shared__ float s_red[8];
    __shared__ float s_bcast;

    const int tid  = threadIdx.x;
    const int warp = tid >> 5;
    const int lane = tid & 31;
    const int b    = blockIdx.x;
    const int len  = lens[b];            // input, independent of scores
    const int i0   = tid * 4;

    cudaGridDependencySynchronize();     // wait for g_scores

    float4 sc = *reinterpret_cast<const float4*>(g_scores + b * L + i0);
    float x0 = (i0 + 0 < len) ? sc.x : -CUDART_INF_F;
    float x1 = (i0 + 1 < len) ? sc.y : -CUDART_INF_F;
    float x2 = (i0 + 2 < len) ? sc.z : -CUDART_INF_F;
    float x3 = (i0 + 3 < len) ? sc.w : -CUDART_INF_F;

    float m = fmaxf(fmaxf(x0, x1), fmaxf(x2, x3));
    #pragma unroll
    for (int o = 16; o; o >>= 1)
        m = fmaxf(m, __shfl_down_sync(0xffffffffu, m, o));
    if (lane == 0) s_red[warp] = m;
    __syncthreads();
    if (warp == 0) {
        float t = (lane < 8) ? s_red[lane] : -CUDART_INF_F;
        #pragma unroll
        for (int o = 4; o; o >>= 1)
            t = fmaxf(t, __shfl_down_sync(0xffffffffu, t, o));
        if (lane == 0) s_bcast = t;
    }
    __syncthreads();
    const float rowmax = s_bcast;

    float e0 = (i0 + 0 < len) ? __expf(x0 - rowmax) : 0.f;
    float e1 = (i0 + 1 < len) ? __expf(x1 - rowmax) : 0.f;
    float e2 = (i0 + 2 < len) ? __expf(x2 - rowmax) : 0.f;
    float e3 = (i0 + 3 < len) ? __expf(x3 - rowmax) : 0.f;

    float s = e0 + e1 + e2 + e3;
    #pragma unroll
    for (int o = 16; o; o >>= 1)
        s += __shfl_down_sync(0xffffffffu, s, o);
    __syncthreads();
    if (lane == 0) s_red[warp] = s;
    __syncthreads();
    if (warp == 0) {
        float t = (lane < 8) ? s_red[lane] : 0.f;
        #pragma unroll
        for (int o = 4; o; o >>= 1)
            t += __shfl_down_sync(0xffffffffu, t, o);
        if (lane == 0) s_bcast = t;
    }
    __syncthreads();
    const float inv = 1.f / s_bcast;

    float4 r = make_float4(e0 * inv, e1 * inv, e2 * inv, e3 * inv);
    *reinterpret_cast<float4*>(out + (size_t)b * L + i0) = r;
}

extern "C" void kernel_launch(void* const* d_in, const int* in_sizes, int n_in,
                              void* d_out, int out_size) {
    const float* questions = (const float*)d_in[0];   // [B2, L, E]
    const int*   lens      = (const int*)d_in[1];     // [B2]
    const float* W         = (const float*)d_in[2];   // [E, E]
    const float* bias      = (const float*)d_in[3];   // [E]
    const float* wv        = (const float*)d_in[4];   // [E, 1]
    float* out             = (float*)d_out;           // [B2, L]

    prep_kernel<<<dim3(4, NPART), 128>>>(W, bias, wv);

    cudaLaunchAttribute attr[1];
    attr[0].id = cudaLaunchAttributeProgrammaticStreamSerialization;
    attr[0].val.programmaticStreamSerializationAllowed = 1;

    {   // scores with PDL
        cudaLaunchConfig_t cfg = {};
        cfg.gridDim  = dim3(L / CHUNK, B2);
        cfg.blockDim = dim3(256);
        cfg.stream   = 0;
        cfg.attrs    = attr;
        cfg.numAttrs = 1;
        cudaLaunchKernelEx(&cfg, scores_kernel, questions, lens);
    }
    {   // softmax with PDL
        cudaLaunchConfig_t cfg = {};
        cfg.gridDim  = dim3(B2);
        cfg.blockDim = dim3(256);
        cfg.stream   = 0;
        cfg.attrs    = attr;
        cfg.numAttrs = 1;
        cudaLaunchKernelEx(&cfg, softmax_kernel, lens, out);
    }
}

// round 14
// speedup vs baseline: 1.3617x; 1.0484x over previous
#include <cuda_runtime.h>
#include <cuda_bf16.h>
#include <math_constants.h>

#define E  512
#define L  1024
#define B2 512
#define CHUNK 128
#define NPART 16     // row-group partial count; scores folds these

__device__ float g_scores[B2 * L];       // raw attention energies
__device__ float g_partial[NPART * E];   // prep partials (folded by scores)

// ---------------------------------------------------------------------------
// Prep: grid (4 col-groups, 16 row-groups) x 512 threads.
// Block (cg, j): rows [32j, 32j+32), cols [128cg, 128cg+128).
// 4 warp-groups of 128 threads each reduce 8 rows, then smem fold.
// NOTE: bias term c is dropped — softmax is shift-invariant, c cancels.
// ---------------------------------------------------------------------------
__global__ __launch_bounds__(512)
void prep_kernel(const float* __restrict__ W,
                 const float* __restrict__ wv) {
    __shared__ float s_wv[32];
    __shared__ float s_part[3][128];
    const int cg  = blockIdx.x;         // 0..3
    const int j   = blockIdx.y;         // 0..NPART-1
    const int t   = threadIdx.x;        // 0..511
    const int col = t & 127;
    const int g   = t >> 7;             // row-group 0..3
    const int e   = cg * 128 + col;
    const int f0  = j * 32 + g * 8;

    if (t < 32) s_wv[t] = __ldg(wv + j * 32 + t);
    __syncthreads();

    float acc = 0.f;
    #pragma unroll
    for (int r = 0; r < 8; ++r)
        acc = fmaf(__ldg(W + (size_t)(f0 + r) * E + e), s_wv[g * 8 + r], acc);

    if (g > 0) s_part[g - 1][col] = acc;
    __syncthreads();
    if (g == 0)
        g_partial[(size_t)j * E + e] =
            acc + s_part[0][col] + s_part[1][col] + s_part[2][col];
}

// ---------------------------------------------------------------------------
// Scores: grid (L/CHUNK, B2), 256 threads = 8 warps, 16 tokens per warp.
// Folds the NPART prep partials while staging s_v (L2-resident, hidden).
// R2-proven inner loop — DO NOT modify. PDL: lens prelude before gridsync.
// ---------------------------------------------------------------------------
__global__ __launch_bounds__(256)
void scores_kernel(const float* __restrict__ q,
                   const int* __restrict__ lens) {
    __shared__ float s_v[E];

    const int tid  = threadIdx.x;
    const int warp = tid >> 5;
    const int lane = tid & 31;
    const int b    = blockIdx.y;
    const int base = blockIdx.x * CHUNK;
    const int len  = lens[b];            // input, independent of prep

    cudaGridDependencySynchronize();     // wait for g_partial

    if (base >= len) return;             // whole chunk masked out

    #pragma unroll
    for (int i = tid; i < E; i += 256) {
        float s = 0.f;
        #pragma unroll
        for (int jj = 0; jj < NPART; ++jj)
            s += g_partial[jj * E + i];
        s_v[i] = s;
    }
    __syncthreads();

    const float4* __restrict__ vv = reinterpret_cast<const float4*>(s_v);
    const float*  __restrict__ qrow = q + (size_t)b * L * E;
    const int tok_end = min(base + CHUNK, len);

    for (int l = base + warp * 16; l < min(base + warp * 16 + 16, tok_end); ++l) {
        const float4* __restrict__ qp =
            reinterpret_cast<const float4*>(qrow + (size_t)l * E);
        float acc = 0.f;
        #pragma unroll
        for (int k = 0; k < 4; ++k) {
            float4 a = __ldg(qp + k * 32 + lane);
            float4 w = vv[k * 32 + lane];
            acc = fmaf(a.x, w.x, acc);
            acc = fmaf(a.y, w.y, acc);
            acc = fmaf(a.z, w.z, acc);
            acc = fmaf(a.w, w.w, acc);
        }
        #pragma unroll
        for (int o = 16; o; o >>= 1)
            acc += __shfl_down_sync(0xffffffffu, acc, o);
        if (lane == 0) g_scores[b * L + l] = acc;
    }
}

// ---------------------------------------------------------------------------
// Softmax over valid prefix. One 256-thread block per row, float4 I/O.
// PDL: lens prelude before gridsync.
// ---------------------------------------------------------------------------
__global__ __launch_bounds__(256)
void softmax_kernel(const int* __restrict__ lens,
                    float* __restrict__ out) {
    __shared__ float s_red[8];
    __shared__ float s_bcast;

    const int tid  = threadIdx.x;
    const int warp = tid >> 5;
    const int lane = tid & 31;
    const int b    = blockIdx.x;
    const int len  = lens[b];            // input, independent of scores
    const int i0   = tid * 4;

    cudaGridDependencySynchronize();     // wait for g_scores

    float4 sc = *reinterpret_cast<const float4*>(g_scores + b * L + i0);
    float x0 = (i0 + 0 < len) ? sc.x : -CUDART_INF_F;
    float x1 = (i0 + 1 < len) ? sc.y : -CUDART_INF_F;
    float x2 = (i0 + 2 < len) ? sc.z : -CUDART_INF_F;
    float x3 = (i0 + 3 < len) ? sc.w : -CUDART_INF_F;

    float m = fmaxf(fmaxf(x0, x1), fmaxf(x2, x3));
    #pragma unroll
    for (int o = 16; o; o >>= 1)
        m = fmaxf(m, __shfl_down_sync(0xffffffffu, m, o));
    if (lane == 0) s_red[warp] = m;
    __syncthreads();
    if (warp == 0) {
        float t = (lane < 8) ? s_red[lane] : -CUDART_INF_F;
        #pragma unroll
        for (int o = 4; o; o >>= 1)
            t = fmaxf(t, __shfl_down_sync(0xffffffffu, t, o));
        if (lane == 0) s_bcast = t;
    }
    __syncthreads();
    const float rowmax = s_bcast;

    float e0 = (i0 + 0 < len) ? __expf(x0 - rowmax) : 0.f;
    float e1 = (i0 + 1 < len) ? __expf(x1 - rowmax) : 0.f;
    float e2 = (i0 + 2 < len) ? __expf(x2 - rowmax) : 0.f;
    float e3 = (i0 + 3 < len) ? __expf(x3 - rowmax) : 0.f;

    float s = e0 + e1 + e2 + e3;
    #pragma unroll
    for (int o = 16; o; o >>= 1)
        s += __shfl_down_sync(0xffffffffu, s, o);
    __syncthreads();
    if (lane == 0) s_red[warp] = s;
    __syncthreads();
    if (warp == 0) {
        float t = (lane < 8) ? s_red[lane] : 0.f;
        #pragma unroll
        for (int o = 4; o; o >>= 1)
            t += __shfl_down_sync(0xffffffffu, t, o);
        if (lane == 0) s_bcast = t;
    }
    __syncthreads();
    const float inv = 1.f / s_bcast;

    float4 r = make_float4(e0 * inv, e1 * inv, e2 * inv, e3 * inv);
    *reinterpret_cast<float4*>(out + (size_t)b * L + i0) = r;
}

extern "C" void kernel_launch(void* const* d_in, const int* in_sizes, int n_in,
                              void* d_out, int out_size) {
    const float* questions = (const float*)d_in[0];   // [B2, L, E]
    const int*   lens      = (const int*)d_in[1];     // [B2]
    const float* W         = (const float*)d_in[2];   // [E, E]
    const float* wv        = (const float*)d_in[4];   // [E, 1]
    float* out             = (float*)d_out;           // [B2, L]

    prep_kernel<<<dim3(4, NPART), 512>>>(W, wv);

    cudaLaunchAttribute attr[1];
    attr[0].id = cudaLaunchAttributeProgrammaticStreamSerialization;
    attr[0].val.programmaticStreamSerializationAllowed = 1;

    {   // scores with PDL
        cudaLaunchConfig_t cfg = {};
        cfg.gridDim  = dim3(L / CHUNK, B2);
        cfg.blockDim = dim3(256);
        cfg.stream   = 0;
        cfg.attrs    = attr;
        cfg.numAttrs = 1;
        cudaLaunchKernelEx(&cfg, scores_kernel, questions, lens);
    }
    {   // softmax with PDL
        cudaLaunchConfig_t cfg = {};
        cfg.gridDim  = dim3(B2);
        cfg.blockDim = dim3(256);
        cfg.stream   = 0;
        cfg.attrs    = attr;
        cfg.numAttrs = 1;
        cudaLaunchKernelEx(&cfg, softmax_kernel, lens, out);
    }
}